// round 13
// baseline (speedup 1.0000x reference)
#include <cuda_runtime.h>
#include <math.h>

#define LSEQ 1024
#define NDIM 256

// Output layout (floats): c_all, y_all, GBT_A, GBT_B
#define OFF_Y    (LSEQ * NDIM)
#define OFF_GBTA (LSEQ * NDIM + LSEQ)
#define OFF_GBTB (LSEQ * NDIM + LSEQ + LSEQ * NDIM * NDIM)

// Writer tables (validated in R5)
__device__ float g_rowv[LSEQ * NDIM];
__device__ float g_colv[LSEQ * NDIM];
__device__ float g_xd  [LSEQ * NDIM];
__device__ int   g_Ei  [LSEQ * NDIM];
__device__ int   g_Ej  [LSEQ * NDIM];

__device__ __forceinline__ float pow2i(int n) {
    return (n < -126) ? 0.0f : __int_as_float((n + 127) << 23);
}

// ---------------------------------------------------------------------------
// Kernel 1: writer factor tables + GBT_B (validated).
// ---------------------------------------------------------------------------
__global__ void params_kernel(float* __restrict__ gbtb)
{
    int k = blockIdx.x;
    int j = threadIdx.x;
    float ss = 1.0f / (float)(k + 1);
    float hh = 0.5f * ss;
    float rj = sqrtf(2.0f * (float)j + 1.0f);
    float d  = fmaf(hh, (float)(j + 1), 1.0f);
    float invd = 1.0f / d;
    float g = fmaf(-hh, (float)j, 1.0f) * invd;
    if (g == 0.0f) g = 1e-30f;

    int e; float m = frexpf(g, &e);
    __shared__ float sm[NDIM];
    __shared__ int   se[NDIM];
    sm[j] = m; se[j] = e;
    __syncthreads();
    #pragma unroll
    for (int off = 1; off < NDIM; off <<= 1) {
        float pm = 0.0f; int pe = 0;
        bool act = (j >= off);
        if (act) { pm = sm[j - off]; pe = se[j - off]; }
        __syncthreads();
        if (act) {
            m = m * pm; e = e + pe;
            if (fabsf(m) < 0.5f) { m *= 2.0f; e -= 1; }
            sm[j] = m; se[j] = e;
        }
        __syncthreads();
    }
    float Mj = m;
    float Mi = 1.0f; int Ei = 0;
    if (j > 0) { Mi = sm[j - 1]; Ei = se[j - 1]; }

    float rd  = rj * invd;
    int   idx = k * NDIM + j;
    g_rowv[idx] = -2.0f * hh * rd * Mi;
    g_colv[idx] = rd / Mj;
    g_xd[idx]   = fmaf(-hh, (float)(j + 1), 1.0f) * invd;
    g_Ei[idx]   = Ei;
    g_Ej[idx]   = se[j];
    gbtb[idx]   = ss * rd * Mi * pow2i(Ei);
}

// Reciprocal table in smem, padded (m + (m>>3)) -> conflict-free lane strides
#define RT_MMAX 2312
#define RT_SIZE (RT_MMAX + (RT_MMAX >> 3) + 4)
#define FULLM 0xffffffffu

// Build step constants from recips Q and scalar TF (=2k for that step).
// All data-independent of the state -> runs off the critical path.
#define PREP(Q, TF, A1, RQ, GG, AA, GHR, KK)                                  \
do {                                                                          \
    _Pragma("unroll")                                                         \
    for (int e = 0; e < 8; e++) {                                             \
        A1[e] = ((TF) - ip1[e]) * Q[e];                                       \
        RQ[e] = rr[e] * Q[e];                                                 \
        GG[e] = A1[e] + Q[e];                                                 \
    }                                                                         \
    AA[0] = GG[0];                                                            \
    _Pragma("unroll")                                                         \
    for (int e = 1; e < 8; e++) AA[e] = AA[e - 1] * GG[e];                    \
    {                                                                         \
        float Gs = 1.0f;                                                      \
        GHR[7] = rr[7];                                                       \
        _Pragma("unroll")                                                     \
        for (int e = 6; e >= 0; e--) { Gs *= GG[e + 1]; GHR[e] = Gs * rr[e]; }\
    }                                                                         \
    {                                                                         \
        float A = AA[7], Ao;                                                  \
        Ao = __shfl_up_sync(FULLM, A, 1);                                     \
        KK[0] = (lane >= 1) ? A : 0.0f; if (lane >= 1) A *= Ao;               \
        Ao = __shfl_up_sync(FULLM, A, 2);                                     \
        KK[1] = (lane >= 2) ? A : 0.0f; if (lane >= 2) A *= Ao;               \
        Ao = __shfl_up_sync(FULLM, A, 4);                                     \
        KK[2] = (lane >= 4) ? A : 0.0f; if (lane >= 4) A *= Ao;               \
        Ao = __shfl_up_sync(FULLM, A, 8);                                     \
        KK[3] = (lane >= 8) ? A : 0.0f; if (lane >= 8) A *= Ao;               \
        Ao = __shfl_up_sync(FULLM, A, 16);                                    \
        KK[4] = (lane >= 16) ? A : 0.0f;                                      \
    }                                                                         \
} while (0)

// One scan step using constant set C (A1/RQ/GG/AA/GHR/KK + SFC). Prefetches
// recips for step kk+1 into QN and builds next constant set N via PREP.
#define SCAN_STEP(kk, SFC, A1, RQ, GG, AA, GHR, KK,                           \
                  QN, TFN, SFN, A1n, RQn, GGn, AAn, GHRn, KKn)                \
do {                                                                          \
    int kt = ((kk) < LSEQ) ? (kk) : (LSEQ - 1);                               \
    SFN = 2.0f * shf[kt];                                                     \
    TFN = 2.0f * (float)((kk) + 1);                                           \
    int m0 = 2 * (kk) + 2 + mbase;                                            \
    _Pragma("unroll")                                                         \
    for (int e = 0; e < 8; e++) {                                             \
        int mm = m0 + e;                                                      \
        QN[e] = rtab[mm + (mm >> 3)];                                         \
    }                                                                         \
    float wt[8];                                                              \
    _Pragma("unroll")                                                         \
    for (int e = 0; e < 8; e++) {                                             \
        float s = (SFC) - Sx[e];                                              \
        wt[e] = fmaf(A1[e], cc[e], RQ[e] * s);                                \
    }                                                                         \
    /* critical-path B composite: tree */                                     \
    float B;                                                                  \
    {                                                                         \
        float p0 = GHR[0] * wt[0], p1 = GHR[1] * wt[1];                       \
        float p2 = GHR[2] * wt[2], p3 = GHR[3] * wt[3];                       \
        float p4 = GHR[4] * wt[4], p5 = GHR[5] * wt[5];                       \
        float p6 = GHR[6] * wt[6], p7 = GHR[7] * wt[7];                       \
        B = ((p0 + p1) + (p2 + p3)) + ((p4 + p5) + (p6 + p7));                \
    }                                                                         \
    /* unconditional masked KS scan (K=0 below off) */                        \
    {                                                                         \
        float Bo;                                                             \
        Bo = __shfl_up_sync(FULLM, B, 1);  B = fmaf(KK[0], Bo, B);            \
        Bo = __shfl_up_sync(FULLM, B, 2);  B = fmaf(KK[1], Bo, B);            \
        Bo = __shfl_up_sync(FULLM, B, 4);  B = fmaf(KK[2], Bo, B);            \
        Bo = __shfl_up_sync(FULLM, B, 8);  B = fmaf(KK[3], Bo, B);            \
        Bo = __shfl_up_sync(FULLM, B, 16); B = fmaf(KK[4], Bo, B);            \
    }                                                                         \
    /* off-path (fills scan latency): lane Bb partials + next constants */    \
    float Bb[7];                                                              \
    Bb[0] = rr[0] * wt[0];                                                    \
    _Pragma("unroll")                                                         \
    for (int e = 1; e < 7; e++) Bb[e] = fmaf(GG[e], Bb[e - 1], rr[e] * wt[e]);\
    PREP(QN, TFN, A1n, RQn, GGn, AAn, GHRn, KKn);                             \
    float V = __shfl_up_sync(FULLM, B, 1);                                    \
    if (lane == 0) V = 0.0f;                                                  \
    Sx[0] = V;                                                                \
    cc[0] = fmaf(-RQ[0], V, wt[0]);                                           \
    _Pragma("unroll")                                                         \
    for (int e = 1; e < 8; e++) {                                             \
        float Sn = fmaf(AA[e - 1], V, Bb[e - 1]);                             \
        cc[e] = fmaf(-RQ[e], Sn, wt[e]);                                      \
        Sx[e] = Sn;                                                           \
    }                                                                         \
    cptr[0] = make_float4(cc[0], cc[1], cc[2], cc[3]);                        \
    cptr[1] = make_float4(cc[4], cc[5], cc[6], cc[7]);                        \
    cptr += NDIM / 4;                                                         \
} while (0)

// ---------------------------------------------------------------------------
// Kernel 2 (fused): block 0 = sequential scan, blocks 1.. = GBT_A writer.
// ---------------------------------------------------------------------------
__global__ void __launch_bounds__(256) fused_kernel(
    const float* __restrict__ f,
    const float* __restrict__ init_state,
    float* __restrict__ out)
{
    if (blockIdx.x != 0) {
        // ----------------- GBT_A writer (validated) ------------------------
        int wb = blockIdx.x - 1;
        int k  = wb >> 3;
        int i0 = (wb & 7) * 32;
        int tx = threadIdx.x & 63;
        int ty = threadIdx.x >> 6;
        int jb = tx * 4;
        const float4 cv = *reinterpret_cast<const float4*>(&g_colv[k * NDIM + jb]);
        const int4   ev = *reinterpret_cast<const int4*>  (&g_Ej  [k * NDIM + jb]);
        float* base = out + (size_t)OFF_GBTA + (size_t)k * (NDIM * NDIM);
        #pragma unroll
        for (int rw = 0; rw < 8; rw++) {
            int i = i0 + ty + rw * 4;
            float rv = g_rowv[k * NDIM + i];
            int   Ei = g_Ei  [k * NDIM + i];
            float xd = g_xd  [k * NDIM + i];
            float4 o;
            o.x = (jb + 0 > i) ? 0.0f : ((jb + 0 == i) ? xd : rv * cv.x * pow2i(Ei - ev.x));
            o.y = (jb + 1 > i) ? 0.0f : ((jb + 1 == i) ? xd : rv * cv.y * pow2i(Ei - ev.y));
            o.z = (jb + 2 > i) ? 0.0f : ((jb + 2 == i) ? xd : rv * cv.z * pow2i(Ei - ev.z));
            o.w = (jb + 3 > i) ? 0.0f : ((jb + 3 == i) ? xd : rv * cv.w * pow2i(Ei - ev.w));
            *reinterpret_cast<float4*>(&base[(size_t)i * NDIM + jb]) = o;
        }
        return;
    }

    // --------------------- scan block ------------------------------------
    __shared__ float shf[LSEQ];
    __shared__ float rtab[RT_SIZE];
    for (int t = threadIdx.x; t < LSEQ; t += 256) shf[t] = f[t];
    for (int mth = threadIdx.x; mth < RT_MMAX; mth += 256) {
        float v = (mth == 0) ? 0.0f : (1.0f / (float)mth);
        rtab[mth + (mth >> 3)] = v;
    }
    __syncthreads();
    if (threadIdx.x >= 32) return;
    int lane = threadIdx.x;
    int mbase = lane * 8 + 1;

    float rr[8], ip1[8], cc[8], Sx[8];
    #pragma unroll
    for (int e = 0; e < 8; e++) {
        int i  = lane * 8 + e;
        rr[e]  = sqrtf(2.0f * (float)i + 1.0f);
        ip1[e] = (float)(i + 1);
        cc[e]  = init_state[i];
    }
    // Initial exclusive prefix of r_j * c_j
    {
        float lex[8]; float run = 0.0f;
        #pragma unroll
        for (int e = 0; e < 8; e++) { lex[e] = run; run = fmaf(rr[e], cc[e], run); }
        float tot = run;
        #pragma unroll
        for (int off = 1; off < 32; off <<= 1) {
            float v = __shfl_up_sync(FULLM, tot, off);
            if (lane >= off) tot += v;
        }
        float carry = __shfl_up_sync(FULLM, tot, 1);
        if (lane == 0) carry = 0.0f;
        #pragma unroll
        for (int e = 0; e < 8; e++) Sx[e] = carry + lex[e];
    }

    float4* cptr = reinterpret_cast<float4*>(out) + lane * 2;

    // Constant sets A and B (ping-pong)
    float qA[8], qB[8];
    float a1A[8], rqA[8], ggA[8], AaA[8], GhrA[8], KA[5];
    float a1B[8], rqB[8], ggB[8], AaB[8], GhrB[8], KB[5];
    float TfA, TfB, sfA, sfB;

    // Bootstrap step 1 (T=2): recips m = 2 + (i+1)
    #pragma unroll
    for (int e = 0; e < 8; e++) {
        int mm = 2 + mbase + e;
        qA[e] = rtab[mm + (mm >> 3)];
    }
    TfA = 2.0f; sfA = 2.0f * shf[0];
    PREP(qA, TfA, a1A, rqA, ggA, AaA, GhrA, KA);

    #pragma unroll 1
    for (int k = 1; k <= LSEQ; k += 2) {
        SCAN_STEP(k,     sfA, a1A, rqA, ggA, AaA, GhrA, KA,
                  qB, TfB, sfB, a1B, rqB, ggB, AaB, GhrB, KB);
        SCAN_STEP(k + 1, sfB, a1B, rqB, ggB, AaB, GhrB, KB,
                  qA, TfA, sfA, a1A, rqA, ggA, AaA, GhrA, KA);
    }
}

// ---------------------------------------------------------------------------
// Kernel 3: y_all[k] = sum_i c_all[k][i]
// ---------------------------------------------------------------------------
__global__ void y_kernel(const float* __restrict__ c_all, float* __restrict__ y_all)
{
    int row  = blockIdx.x * 8 + (threadIdx.x >> 5);
    int lane = threadIdx.x & 31;
    const float4* p = reinterpret_cast<const float4*>(c_all + (size_t)row * NDIM);
    float4 a = p[lane * 2], b = p[lane * 2 + 1];
    float s = ((a.x + a.y) + (a.z + a.w)) + ((b.x + b.y) + (b.z + b.w));
    #pragma unroll
    for (int off = 16; off >= 1; off >>= 1)
        s += __shfl_down_sync(FULLM, s, off);
    if (lane == 0) y_all[row] = s;
}

extern "C" void kernel_launch(void* const* d_in, const int* in_sizes, int n_in,
                              void* d_out, int out_size)
{
    int fi = 0, ii = 1;
    if (n_in >= 4 && in_sizes[0] == NDIM * NDIM) { fi = 2; ii = 3; }
    const float* f    = (const float*)d_in[fi];
    const float* init = (const float*)d_in[ii];
    float* out = (float*)d_out;

    params_kernel<<<LSEQ, NDIM>>>(out + (size_t)OFF_GBTB);
    fused_kernel<<<1 + LSEQ * 8, 256>>>(f, init, out);
    y_kernel<<<LSEQ / 8, 256>>>(out, out + (size_t)OFF_Y);
}